// round 7
// baseline (speedup 1.0000x reference)
#include <cuda_runtime.h>
#include <cuda_bf16.h>
#include <cstdint>

#define NNODE 50000
#define NEDGE 800000
#define DIM   64
#define NREL  65
#define TILE  256
#define EPB   2048
#define NB    ((NEDGE + EPB - 1) / EPB)
#define NTILES_MAX ((NEDGE + TILE - 1) / TILE + NREL)
#define SAK   72    // smem row stride in bf16 units (144B; conflict-free)
#define SBK   72

// ---- scratch (static device globals; no allocation) ----
__device__ int   g_cnt[NNODE * NREL];
__device__ int   g_blockHist[NB * NREL];
__device__ int   g_relCnt[NREL];
__device__ int   g_relOff[NREL + 1];
__device__ int   g_tileBase[NREL + 1];
__device__ int   g_tileRel[NTILES_MAX];
__device__ int   g_tileStart[NTILES_MAX];
__device__ int   g_numTiles;
__device__ int   g_srcP[NEDGE];
__device__ int   g_dstP[NEDGE];
__device__ float g_normP[NEDGE];
__device__ float g_h[NNODE * DIM];
// pre-split bf16 buffers: row = 128 bf16 (hi[0:64], lo[64:128]) = 256B
__device__ __nv_bfloat16 g_Xs[(size_t)NNODE * 128];
__device__ __nv_bfloat16 g_Hs[(size_t)NNODE * 128];
// W splits: 66 slots (65 relations + self-loop W), [slot][n][128]: hi(k) 0:64, lo(k) 64:128
__device__ __nv_bfloat16 g_Ws1[(size_t)(NREL + 1) * DIM * 128];
__device__ __nv_bfloat16 g_Ws2[(size_t)(NREL + 1) * DIM * 128];

#define MMA_BF16(c, a, b0, b1)                                                   \
    asm volatile("mma.sync.aligned.m16n8k16.row.col.f32.bf16.bf16.f32 "          \
                 "{%0,%1,%2,%3},{%4,%5,%6,%7},{%8,%9},{%0,%1,%2,%3};"            \
                 : "+f"(c[0]), "+f"(c[1]), "+f"(c[2]), "+f"(c[3])                \
                 : "r"(a[0]), "r"(a[1]), "r"(a[2]), "r"(a[3]), "r"(b0), "r"(b1))

// SMEM layout (bytes)
#define SM_DST  0
#define SM_NRM  1024
#define SM_AH   2048
#define ASZ     (TILE * SAK * 2)                 // 36864
#define SM_AL   (SM_AH + ASZ + 16)
#define SM_BH   (SM_AL + ASZ + 16)
#define BSZ     (DIM * SBK * 2)                  // 9216
#define SM_BL   (SM_BH + BSZ + 16)
#define SM_TOT  (SM_BL + BSZ)                    // 94256

// ---------------------------------------------------------------- histogram
__global__ void __launch_bounds__(256) k_hist(const int* __restrict__ dst,
                                              const int* __restrict__ et) {
    __shared__ int h[NREL];
    int tid = threadIdx.x, b = blockIdx.x;
    if (tid < NREL) h[tid] = 0;
    __syncthreads();
    int s = b * EPB, e_end = min(s + EPB, NEDGE);
    for (int e = s + tid; e < e_end; e += 256) {
        int r = et[e];
        atomicAdd(&h[r], 1);
        atomicAdd(&g_cnt[dst[e] * NREL + r], 1);
    }
    __syncthreads();
    if (tid < NREL) g_blockHist[b * NREL + tid] = h[tid];
}

// ---------------------------------------------------------------- per-relation block scan
__global__ void k_scanRel() {
    __shared__ int v[NB];
    int r = blockIdx.x, tid = threadIdx.x;
    for (int b = tid; b < NB; b += blockDim.x) v[b] = g_blockHist[b * NREL + r];
    __syncthreads();
    if (tid == 0) {
        int acc = 0;
        for (int b = 0; b < NB; b++) { int t = v[b]; v[b] = acc; acc += t; }
        g_relCnt[r] = acc;
    }
    __syncthreads();
    for (int b = tid; b < NB; b += blockDim.x) g_blockHist[b * NREL + r] = v[b];
}

// ---------------------------------------------------------------- relation offsets (parallel scan)
__global__ void k_scan() {
    __shared__ int a[128], b2[128];
    int t = threadIdx.x;
    int c  = (t < NREL) ? g_relCnt[t] : 0;
    int nt = (c + TILE - 1) / TILE;
    a[t] = c; b2[t] = nt;
    __syncthreads();
    for (int off = 1; off < 128; off <<= 1) {
        int av = a[t], bv = b2[t];
        int au = (t >= off) ? a[t - off] : 0;
        int bu = (t >= off) ? b2[t - off] : 0;
        __syncthreads();
        a[t] = av + au; b2[t] = bv + bu;
        __syncthreads();
    }
    if (t < NREL) { g_relOff[t] = a[t] - c; g_tileBase[t] = b2[t] - nt; }
    if (t == NREL - 1) {
        g_relOff[NREL] = a[t];
        g_tileBase[NREL] = b2[t];
        g_numTiles = b2[t];
    }
}

// ---------------------------------------------------------------- parallel tile table
__global__ void k_tiles() {
    int t = blockIdx.x * blockDim.x + threadIdx.x;
    if (t >= g_numTiles) return;
    int lo = 0, hi = NREL;
    while (lo + 1 < hi) {
        int mid = (lo + hi) >> 1;
        if (g_tileBase[mid] <= t) lo = mid; else hi = mid;
    }
    g_tileRel[t]   = lo;
    g_tileStart[t] = g_relOff[lo] + (t - g_tileBase[lo]) * TILE;
}

// ---------------------------------------------------------------- scatter sorted arrays
__global__ void __launch_bounds__(256) k_scatter(const int* __restrict__ src,
                                                 const int* __restrict__ dst,
                                                 const int* __restrict__ et) {
    __shared__ int cur[NREL];
    int tid = threadIdx.x, b = blockIdx.x;
    if (tid < NREL) cur[tid] = g_relOff[tid] + g_blockHist[b * NREL + tid];
    __syncthreads();
    int s = b * EPB, e_end = min(s + EPB, NEDGE);
    for (int e = s + tid; e < e_end; e += 256) {
        int r = et[e], d = dst[e];
        int pos = atomicAdd(&cur[r], 1);
        g_srcP[pos]  = src[e];
        g_dstP[pos]  = d;
        g_normP[pos] = 1.0f / (float)max(g_cnt[d * NREL + r], 1);
    }
}

// ---------------------------------------------------------------- W split (both layers in one launch)
__global__ void __launch_bounds__(256) k_wsplit(const float* __restrict__ W1,
                                                const float* __restrict__ Wl1,
                                                const float* __restrict__ W2,
                                                const float* __restrict__ Wl2,
                                                __nv_bfloat16* __restrict__ o1,
                                                __nv_bfloat16* __restrict__ o2) {
    int rb = blockIdx.x;
    int layer = rb >= (NREL + 1);
    int r = layer ? rb - (NREL + 1) : rb;
    const float* W  = layer ? W2 : W1;
    const float* Wl = layer ? Wl2 : Wl1;
    __nv_bfloat16* out = layer ? o2 : o1;
    const float* src = (r < NREL) ? (W + (size_t)r * DIM * DIM) : Wl;
    int t = threadIdx.x;
    int n = t >> 2, kc = (t & 3) * 16;
    __nv_bfloat16 h[16], l[16];
#pragma unroll
    for (int kk = 0; kk < 16; kk++) {
        float v = src[(kc + kk) * DIM + n];
        __nv_bfloat16 hh = __float2bfloat16_rn(v);
        h[kk] = hh;
        l[kk] = __float2bfloat16_rn(v - __bfloat162float(hh));
    }
    __nv_bfloat16* o = out + ((size_t)(r * DIM + n) * 128 + kc);
    *(uint4*)o        = *(uint4*)&h[0];
    *(uint4*)(o + 8)  = *(uint4*)&h[8];
    *(uint4*)(o + 64) = *(uint4*)&l[0];
    *(uint4*)(o + 72) = *(uint4*)&l[8];
}

// ---------------------------------------------------------------- X split
__global__ void k_xsplit(const float* __restrict__ X, __nv_bfloat16* __restrict__ Xs) {
    int i = blockIdx.x * blockDim.x + threadIdx.x;
    if (i >= NNODE * 8) return;
    int row = i >> 3, seg = i & 7;
    const float4* p = (const float4*)(X + (size_t)row * DIM + seg * 8);
    float4 v0 = p[0], v1 = p[1];
    float vv[8] = {v0.x, v0.y, v0.z, v0.w, v1.x, v1.y, v1.z, v1.w};
    __nv_bfloat16 h[8], l[8];
#pragma unroll
    for (int j = 0; j < 8; j++) {
        __nv_bfloat16 hh = __float2bfloat16_rn(vv[j]);
        h[j] = hh;
        l[j] = __float2bfloat16_rn(vv[j] - __bfloat162float(hh));
    }
    __nv_bfloat16* o = Xs + (size_t)row * 128 + seg * 8;
    *(uint4*)o        = *(uint4*)h;
    *(uint4*)(o + 64) = *(uint4*)l;
}

// ---------------------------------------------------------------- relu + split (layer boundary)
__global__ void k_relu_split(const float* __restrict__ O, __nv_bfloat16* __restrict__ Xs) {
    int i = blockIdx.x * blockDim.x + threadIdx.x;
    if (i >= NNODE * 8) return;
    int row = i >> 3, seg = i & 7;
    const float4* p = (const float4*)(O + (size_t)row * DIM + seg * 8);
    float4 v0 = p[0], v1 = p[1];
    float vv[8] = {fmaxf(v0.x, 0.f), fmaxf(v0.y, 0.f), fmaxf(v0.z, 0.f), fmaxf(v0.w, 0.f),
                   fmaxf(v1.x, 0.f), fmaxf(v1.y, 0.f), fmaxf(v1.z, 0.f), fmaxf(v1.w, 0.f)};
    __nv_bfloat16 h[8], l[8];
#pragma unroll
    for (int j = 0; j < 8; j++) {
        __nv_bfloat16 hh = __float2bfloat16_rn(vv[j]);
        h[j] = hh;
        l[j] = __float2bfloat16_rn(vv[j] - __bfloat162float(hh));
    }
    __nv_bfloat16* o = Xs + (size_t)row * 128 + seg * 8;
    *(uint4*)o        = *(uint4*)h;
    *(uint4*)(o + 64) = *(uint4*)l;
}

// ======================= shared mainloop fragment helpers ====================
__device__ __forceinline__ void load_B_tile(char* smem, const __nv_bfloat16* Ws,
                                            int slot, int tid) {
    int n = tid >> 2, c = tid & 3;
    const uint4* wr = (const uint4*)(Ws + ((size_t)(slot * DIM + n) * 128 + (c & 1) * 32 + (c >> 1) * 64));
    char* db = smem + ((c >> 1) ? SM_BL : SM_BH) + n * 144 + (c & 1) * 64;
#pragma unroll
    for (int j = 0; j < 4; j++) ((uint4*)db)[j] = wr[j];
}

// ---------------------------------------------------------------- edge kernel
__global__ void __launch_bounds__(256, 2) k_edges(const __nv_bfloat16* __restrict__ Xs,
                                                  const __nv_bfloat16* __restrict__ Ws,
                                                  float* __restrict__ O) {
    int t = blockIdx.x;
    if (t >= g_numTiles) return;
    int r  = g_tileRel[t];
    int s0 = g_tileStart[t];
    int m  = min(g_relOff[r + 1] - s0, TILE);

    extern __shared__ char smem[];
    int*   sDst  = (int*)(smem + SM_DST);
    float* sNorm = (float*)(smem + SM_NRM);
    int tid = threadIdx.x;

    load_B_tile(smem, Ws, r, tid);

    // gather: one thread per row
    {
        int e = tid;
        char* ah = smem + SM_AH + e * 144;
        char* al = smem + SM_AL + e * 144;
        if (e < m) {
            int sr = g_srcP[s0 + e];
            sDst[e]  = g_dstP[s0 + e];
            sNorm[e] = g_normP[s0 + e];
            const uint4* xr = (const uint4*)(Xs + (size_t)sr * 128);
#pragma unroll
            for (int j = 0; j < 8; j++) ((uint4*)ah)[j] = xr[j];
#pragma unroll
            for (int j = 0; j < 8; j++) ((uint4*)al)[j] = xr[8 + j];
        } else {
            uint4 z = make_uint4(0, 0, 0, 0);
#pragma unroll
            for (int j = 0; j < 8; j++) { ((uint4*)ah)[j] = z; ((uint4*)al)[j] = z; }
        }
    }
    __syncthreads();

    int lane = tid & 31, wid = tid >> 5;
    int g = lane >> 2, tg = lane & 3;
    int m0 = wid * 32;

    float c[2][8][4];
#pragma unroll
    for (int mt = 0; mt < 2; mt++)
#pragma unroll
        for (int n = 0; n < 8; n++) {
            c[mt][n][0] = 0.f; c[mt][n][1] = 0.f; c[mt][n][2] = 0.f; c[mt][n][3] = 0.f;
        }

#pragma unroll
    for (int ks = 0; ks < 4; ks++) {
        int k0 = ks * 16;
        uint32_t ah[2][4], al[2][4];
#pragma unroll
        for (int mt = 0; mt < 2; mt++) {
            const char* pLo = smem + SM_AH + ((m0 + mt * 16 + g) * SAK + k0 + 2 * tg) * 2;
            const char* pHi = pLo + 8 * SAK * 2;
            ah[mt][0] = *(const uint32_t*)pLo;       ah[mt][1] = *(const uint32_t*)pHi;
            ah[mt][2] = *(const uint32_t*)(pLo + 16); ah[mt][3] = *(const uint32_t*)(pHi + 16);
            const char* qLo = smem + SM_AL + ((m0 + mt * 16 + g) * SAK + k0 + 2 * tg) * 2;
            const char* qHi = qLo + 8 * SAK * 2;
            al[mt][0] = *(const uint32_t*)qLo;       al[mt][1] = *(const uint32_t*)qHi;
            al[mt][2] = *(const uint32_t*)(qLo + 16); al[mt][3] = *(const uint32_t*)(qHi + 16);
        }
#pragma unroll
        for (int n = 0; n < 8; n++) {
            uint32_t off = (uint32_t)((n * 8 + g) * SBK + k0 + 2 * tg) * 2;
            uint32_t bh0 = *(const uint32_t*)(smem + SM_BH + off);
            uint32_t bh1 = *(const uint32_t*)(smem + SM_BH + off + 16);
            uint32_t bl0 = *(const uint32_t*)(smem + SM_BL + off);
            uint32_t bl1 = *(const uint32_t*)(smem + SM_BL + off + 16);
#pragma unroll
            for (int mt = 0; mt < 2; mt++) {
                MMA_BF16(c[mt][n], ah[mt], bh0, bh1);
                MMA_BF16(c[mt][n], al[mt], bh0, bh1);
                MMA_BF16(c[mt][n], ah[mt], bl0, bl1);
            }
        }
    }

    // epilogue: norm, shfl-pair, red.global.add.v4
    int  col0 = (tg & 2) * 2;
    bool lead = (tg & 1) == 0;
#pragma unroll
    for (int mt = 0; mt < 2; mt++) {
        int rA = m0 + mt * 16 + g, rB = rA + 8;
        int dA = (rA < m) ? sDst[rA] : -1;
        int dB = (rB < m) ? sDst[rB] : -1;
        float nA = (rA < m) ? sNorm[rA] : 0.f;
        float nB = (rB < m) ? sNorm[rB] : 0.f;
#pragma unroll
        for (int n = 0; n < 8; n++) {
            float x0 = c[mt][n][0] * nA, y0 = c[mt][n][1] * nA;
            float x1 = c[mt][n][2] * nB, y1 = c[mt][n][3] * nB;
            float qx0 = __shfl_xor_sync(0xffffffffu, x0, 1);
            float qy0 = __shfl_xor_sync(0xffffffffu, y0, 1);
            float qx1 = __shfl_xor_sync(0xffffffffu, x1, 1);
            float qy1 = __shfl_xor_sync(0xffffffffu, y1, 1);
            if (lead && dA >= 0) {
                float* o = O + (size_t)dA * DIM + n * 8 + col0;
                asm volatile("red.global.add.v4.f32 [%0], {%1,%2,%3,%4};"
                             :: "l"(o), "f"(x0), "f"(y0), "f"(qx0), "f"(qy0) : "memory");
            }
            if (lead && dB >= 0) {
                float* o = O + (size_t)dB * DIM + n * 8 + col0;
                asm volatile("red.global.add.v4.f32 [%0], {%1,%2,%3,%4};"
                             :: "l"(o), "f"(x1), "f"(y1), "f"(qx1), "f"(qy1) : "memory");
            }
        }
    }
}

// ---------------------------------------------------------------- self-loop: O = X @ Wl (direct write)
__global__ void __launch_bounds__(256, 2) k_selfloop(const __nv_bfloat16* __restrict__ Xs,
                                                     const __nv_bfloat16* __restrict__ Ws,
                                                     float* __restrict__ O) {
    int base = blockIdx.x * TILE;
    int m = min(TILE, NNODE - base);
    extern __shared__ char smem[];
    int tid = threadIdx.x;

    load_B_tile(smem, Ws, NREL, tid);

    {
        int e = tid;
        char* ah = smem + SM_AH + e * 144;
        char* al = smem + SM_AL + e * 144;
        if (e < m) {
            const uint4* xr = (const uint4*)(Xs + (size_t)(base + e) * 128);
#pragma unroll
            for (int j = 0; j < 8; j++) ((uint4*)ah)[j] = xr[j];
#pragma unroll
            for (int j = 0; j < 8; j++) ((uint4*)al)[j] = xr[8 + j];
        } else {
            uint4 z = make_uint4(0, 0, 0, 0);
#pragma unroll
            for (int j = 0; j < 8; j++) { ((uint4*)ah)[j] = z; ((uint4*)al)[j] = z; }
        }
    }
    __syncthreads();

    int lane = tid & 31, wid = tid >> 5;
    int g = lane >> 2, tg = lane & 3;
    int m0 = wid * 32;

    float c[2][8][4];
#pragma unroll
    for (int mt = 0; mt < 2; mt++)
#pragma unroll
        for (int n = 0; n < 8; n++) {
            c[mt][n][0] = 0.f; c[mt][n][1] = 0.f; c[mt][n][2] = 0.f; c[mt][n][3] = 0.f;
        }

#pragma unroll
    for (int ks = 0; ks < 4; ks++) {
        int k0 = ks * 16;
        uint32_t ah[2][4], al[2][4];
#pragma unroll
        for (int mt = 0; mt < 2; mt++) {
            const char* pLo = smem + SM_AH + ((m0 + mt * 16 + g) * SAK + k0 + 2 * tg) * 2;
            const char* pHi = pLo + 8 * SAK * 2;
            ah[mt][0] = *(const uint32_t*)pLo;       ah[mt][1] = *(const uint32_t*)pHi;
            ah[mt][2] = *(const uint32_t*)(pLo + 16); ah[mt][3] = *(const uint32_t*)(pHi + 16);
            const char* qLo = smem + SM_AL + ((m0 + mt * 16 + g) * SAK + k0 + 2 * tg) * 2;
            const char* qHi = qLo + 8 * SAK * 2;
            al[mt][0] = *(const uint32_t*)qLo;       al[mt][1] = *(const uint32_t*)qHi;
            al[mt][2] = *(const uint32_t*)(qLo + 16); al[mt][3] = *(const uint32_t*)(qHi + 16);
        }
#pragma unroll
        for (int n = 0; n < 8; n++) {
            uint32_t off = (uint32_t)((n * 8 + g) * SBK + k0 + 2 * tg) * 2;
            uint32_t bh0 = *(const uint32_t*)(smem + SM_BH + off);
            uint32_t bh1 = *(const uint32_t*)(smem + SM_BH + off + 16);
            uint32_t bl0 = *(const uint32_t*)(smem + SM_BL + off);
            uint32_t bl1 = *(const uint32_t*)(smem + SM_BL + off + 16);
#pragma unroll
            for (int mt = 0; mt < 2; mt++) {
                MMA_BF16(c[mt][n], ah[mt], bh0, bh1);
                MMA_BF16(c[mt][n], al[mt], bh0, bh1);
                MMA_BF16(c[mt][n], ah[mt], bl0, bl1);
            }
        }
    }

    int  col0 = (tg & 2) * 2;
    bool lead = (tg & 1) == 0;
#pragma unroll
    for (int mt = 0; mt < 2; mt++) {
        int rA = m0 + mt * 16 + g, rB = rA + 8;
        bool okA = rA < m, okB = rB < m;
#pragma unroll
        for (int n = 0; n < 8; n++) {
            float x0 = c[mt][n][0], y0 = c[mt][n][1];
            float x1 = c[mt][n][2], y1 = c[mt][n][3];
            float qx0 = __shfl_xor_sync(0xffffffffu, x0, 1);
            float qy0 = __shfl_xor_sync(0xffffffffu, y0, 1);
            float qx1 = __shfl_xor_sync(0xffffffffu, x1, 1);
            float qy1 = __shfl_xor_sync(0xffffffffu, y1, 1);
            if (lead && okA)
                *(float4*)(O + (size_t)(base + rA) * DIM + n * 8 + col0) = make_float4(x0, y0, qx0, qy0);
            if (lead && okB)
                *(float4*)(O + (size_t)(base + rB) * DIM + n * 8 + col0) = make_float4(x1, y1, qx1, qy1);
        }
    }
}

// ---------------------------------------------------------------- relu (final)
__global__ void k_relu(float* __restrict__ O, int n4) {
    int i = blockIdx.x * blockDim.x + threadIdx.x;
    if (i < n4) {
        float4 v = ((float4*)O)[i];
        v.x = fmaxf(v.x, 0.f); v.y = fmaxf(v.y, 0.f);
        v.z = fmaxf(v.z, 0.f); v.w = fmaxf(v.w, 0.f);
        ((float4*)O)[i] = v;
    }
}

// ---------------------------------------------------------------- launch
extern "C" void kernel_launch(void* const* d_in, const int* in_sizes, int n_in,
                              void* d_out, int out_size) {
    const float* x   = (const float*)d_in[0];
    const int*   src = (const int*)d_in[1];
    const int*   dst = (const int*)d_in[2];
    const int*   et  = (const int*)d_in[3];
    const float* W1  = (const float*)d_in[4];
    const float* Wl1 = (const float*)d_in[5];
    const float* W2  = (const float*)d_in[6];
    const float* Wl2 = (const float*)d_in[7];
    float* out = (float*)d_out;

    void* p;
    cudaGetSymbolAddress(&p, g_h);   float* h  = (float*)p;
    cudaGetSymbolAddress(&p, g_Xs);  __nv_bfloat16* Xs = (__nv_bfloat16*)p;
    cudaGetSymbolAddress(&p, g_Hs);  __nv_bfloat16* Hs = (__nv_bfloat16*)p;
    cudaGetSymbolAddress(&p, g_Ws1); __nv_bfloat16* Ws1 = (__nv_bfloat16*)p;
    cudaGetSymbolAddress(&p, g_Ws2); __nv_bfloat16* Ws2 = (__nv_bfloat16*)p;
    void* cntp;
    cudaGetSymbolAddress(&cntp, g_cnt);

    cudaFuncSetAttribute(k_edges,    cudaFuncAttributeMaxDynamicSharedMemorySize, SM_TOT);
    cudaFuncSetAttribute(k_selfloop, cudaFuncAttributeMaxDynamicSharedMemorySize, SM_TOT);

    const int TPB = 256;
    // preprocessing: contention-free counting sort + pre-splits
    cudaMemsetAsync(cntp, 0, (size_t)NNODE * NREL * sizeof(int));
    k_hist<<<NB, TPB>>>(dst, et);
    k_scanRel<<<NREL, 256>>>();
    k_scan<<<1, 128>>>();
    k_tiles<<<(NTILES_MAX + 127) / 128, 128>>>();
    k_scatter<<<NB, TPB>>>(src, dst, et);
    k_wsplit<<<2 * (NREL + 1), 256>>>(W1, Wl1, W2, Wl2, Ws1, Ws2);
    k_xsplit<<<(NNODE * 8 + 255) / 256, 256>>>(x, Xs);

    int nBlocksRows = (NNODE + TILE - 1) / TILE;
    int n4 = NNODE * DIM / 4;

    // layer 1: h = relu(edges(x,W1) + x@Wl1)
    k_selfloop<<<nBlocksRows, TPB, SM_TOT>>>(Xs, Ws1, h);
    k_edges<<<NTILES_MAX, TPB, SM_TOT>>>(Xs, Ws1, h);
    k_relu_split<<<(NNODE * 8 + 255) / 256, 256>>>(h, Hs);

    // layer 2: out = relu(edges(h,W2) + h@Wl2)
    k_selfloop<<<nBlocksRows, TPB, SM_TOT>>>(Hs, Ws2, out);
    k_edges<<<NTILES_MAX, TPB, SM_TOT>>>(Hs, Ws2, out);
    k_relu<<<(n4 + TPB - 1) / TPB, TPB>>>(out, n4);
}

// round 8
// speedup vs baseline: 1.2822x; 1.2822x over previous
#include <cuda_runtime.h>
#include <cuda_bf16.h>
#include <cstdint>

#define NNODE 50000
#define NEDGE 800000
#define DIM   64
#define NREL  65
#define TILE  128
#define EPB   2048
#define NB    ((NEDGE + EPB - 1) / EPB)
#define NTILES_MAX ((NEDGE + TILE - 1) / TILE + NREL)
#define SAK   72    // smem row stride in bf16 units (144B; conflict-free)
#define SBK   72

// ---- scratch (static device globals; no allocation) ----
__device__ int   g_cnt[NNODE * NREL];
__device__ int   g_blockHist[NB * NREL];
__device__ int   g_relCnt[NREL];
__device__ int   g_relOff[NREL + 1];
__device__ int   g_tileBase[NREL + 1];
__device__ int   g_tileRel[NTILES_MAX];
__device__ int   g_tileStart[NTILES_MAX];
__device__ int   g_numTiles;
__device__ int   g_srcP[NEDGE];
__device__ int   g_dstP[NEDGE];
__device__ float g_normP[NEDGE];
__device__ float g_h[NNODE * DIM];
// pre-split bf16 buffers: row = 128 bf16 (hi[0:64], lo[64:128]) = 256B
__device__ __nv_bfloat16 g_Xs[(size_t)NNODE * 128];
__device__ __nv_bfloat16 g_Hs[(size_t)NNODE * 128];
// W splits: 66 slots (65 relations + self-loop W), [slot][n][128]: hi(k) 0:64, lo(k) 64:128
__device__ __nv_bfloat16 g_Ws1[(size_t)(NREL + 1) * DIM * 128];
__device__ __nv_bfloat16 g_Ws2[(size_t)(NREL + 1) * DIM * 128];

#define MMA_BF16(c, a, b0, b1)                                                   \
    asm volatile("mma.sync.aligned.m16n8k16.row.col.f32.bf16.bf16.f32 "          \
                 "{%0,%1,%2,%3},{%4,%5,%6,%7},{%8,%9},{%0,%1,%2,%3};"            \
                 : "+f"(c[0]), "+f"(c[1]), "+f"(c[2]), "+f"(c[3])                \
                 : "r"(a[0]), "r"(a[1]), "r"(a[2]), "r"(a[3]), "r"(b0), "r"(b1))

#define CP16(dst_u32, src_ptr)                                                   \
    asm volatile("cp.async.cg.shared.global [%0], [%1], 16;"                     \
                 :: "r"(dst_u32), "l"(src_ptr))
#define CP_COMMIT() asm volatile("cp.async.commit_group;")
#define CP_WAIT0()  asm volatile("cp.async.wait_group 0;")

__device__ __forceinline__ uint32_t smem_u32(const void* p) {
    uint32_t a;
    asm("{ .reg .u64 t; cvta.to.shared.u64 t, %1; cvt.u32.u64 %0, t; }"
        : "=r"(a) : "l"(p));
    return a;
}

// SMEM layout (bytes)
#define SM_DST  0
#define SM_NRM  512
#define SM_AH   1024
#define ASZ     (TILE * SAK * 2)                 // 18432
#define SM_AL   (SM_AH + ASZ + 16)               // 19472
#define SM_BH   (SM_AL + ASZ + 16)               // 37920
#define BSZ     (DIM * SBK * 2)                  // 9216
#define SM_BL   (SM_BH + BSZ + 16)               // 47152
#define SM_TOT  (SM_BL + BSZ)                    // 56368

// ---------------------------------------------------------------- histogram
__global__ void __launch_bounds__(256) k_hist(const int* __restrict__ dst,
                                              const int* __restrict__ et) {
    __shared__ int h[NREL];
    int tid = threadIdx.x, b = blockIdx.x;
    if (tid < NREL) h[tid] = 0;
    __syncthreads();
    int s = b * EPB, e_end = min(s + EPB, NEDGE);
    for (int e = s + tid; e < e_end; e += 256) {
        int r = et[e];
        atomicAdd(&h[r], 1);
        atomicAdd(&g_cnt[dst[e] * NREL + r], 1);
    }
    __syncthreads();
    if (tid < NREL) g_blockHist[b * NREL + tid] = h[tid];
}

// ---------------------------------------------------------------- per-relation block scan (parallel)
__global__ void __launch_bounds__(128) k_scanRel() {
    __shared__ int ts[128];
    int r = blockIdx.x, t = threadIdx.x;
    int base = t * 4;
    int v[4];
#pragma unroll
    for (int i = 0; i < 4; i++)
        v[i] = (base + i < NB) ? g_blockHist[(base + i) * NREL + r] : 0;
    int sum = v[0] + v[1] + v[2] + v[3];
    ts[t] = sum;
    __syncthreads();
    for (int off = 1; off < 128; off <<= 1) {
        int add = (t >= off) ? ts[t - off] : 0;
        __syncthreads();
        ts[t] += add;
        __syncthreads();
    }
    if (t == 127) g_relCnt[r] = ts[127];
    int run = ts[t] - sum;
#pragma unroll
    for (int i = 0; i < 4; i++) {
        if (base + i < NB) {
            int tmp = v[i];
            g_blockHist[(base + i) * NREL + r] = run;
            run += tmp;
        }
    }
}

// ---------------------------------------------------------------- relation offsets (parallel scan)
__global__ void k_scan() {
    __shared__ int a[128], b2[128];
    int t = threadIdx.x;
    int c  = (t < NREL) ? g_relCnt[t] : 0;
    int nt = (c + TILE - 1) / TILE;
    a[t] = c; b2[t] = nt;
    __syncthreads();
    for (int off = 1; off < 128; off <<= 1) {
        int av = a[t], bv = b2[t];
        int au = (t >= off) ? a[t - off] : 0;
        int bu = (t >= off) ? b2[t - off] : 0;
        __syncthreads();
        a[t] = av + au; b2[t] = bv + bu;
        __syncthreads();
    }
    if (t < NREL) { g_relOff[t] = a[t] - c; g_tileBase[t] = b2[t] - nt; }
    if (t == NREL - 1) {
        g_relOff[NREL] = a[t];
        g_tileBase[NREL] = b2[t];
        g_numTiles = b2[t];
    }
}

// ---------------------------------------------------------------- parallel tile table
__global__ void k_tiles() {
    int t = blockIdx.x * blockDim.x + threadIdx.x;
    if (t >= g_numTiles) return;
    int lo = 0, hi = NREL;
    while (lo + 1 < hi) {
        int mid = (lo + hi) >> 1;
        if (g_tileBase[mid] <= t) lo = mid; else hi = mid;
    }
    g_tileRel[t]   = lo;
    g_tileStart[t] = g_relOff[lo] + (t - g_tileBase[lo]) * TILE;
}

// ---------------------------------------------------------------- scatter sorted arrays
__global__ void __launch_bounds__(256) k_scatter(const int* __restrict__ src,
                                                 const int* __restrict__ dst,
                                                 const int* __restrict__ et) {
    __shared__ int cur[NREL];
    int tid = threadIdx.x, b = blockIdx.x;
    if (tid < NREL) cur[tid] = g_relOff[tid] + g_blockHist[b * NREL + tid];
    __syncthreads();
    int s = b * EPB, e_end = min(s + EPB, NEDGE);
    for (int e = s + tid; e < e_end; e += 256) {
        int r = et[e], d = dst[e];
        int pos = atomicAdd(&cur[r], 1);
        g_srcP[pos]  = src[e];
        g_dstP[pos]  = d;
        g_normP[pos] = 1.0f / (float)max(g_cnt[d * NREL + r], 1);
    }
}

// ---------------------------------------------------------------- W split (both layers in one launch)
__global__ void __launch_bounds__(256) k_wsplit(const float* __restrict__ W1,
                                                const float* __restrict__ Wl1,
                                                const float* __restrict__ W2,
                                                const float* __restrict__ Wl2,
                                                __nv_bfloat16* __restrict__ o1,
                                                __nv_bfloat16* __restrict__ o2) {
    int rb = blockIdx.x;
    int layer = rb >= (NREL + 1);
    int r = layer ? rb - (NREL + 1) : rb;
    const float* W  = layer ? W2 : W1;
    const float* Wl = layer ? Wl2 : Wl1;
    __nv_bfloat16* out = layer ? o2 : o1;
    const float* src = (r < NREL) ? (W + (size_t)r * DIM * DIM) : Wl;
    int t = threadIdx.x;
    int n = t >> 2, kc = (t & 3) * 16;
    __nv_bfloat16 h[16], l[16];
#pragma unroll
    for (int kk = 0; kk < 16; kk++) {
        float v = src[(kc + kk) * DIM + n];
        __nv_bfloat16 hh = __float2bfloat16_rn(v);
        h[kk] = hh;
        l[kk] = __float2bfloat16_rn(v - __bfloat162float(hh));
    }
    __nv_bfloat16* o = out + ((size_t)(r * DIM + n) * 128 + kc);
    *(uint4*)o        = *(uint4*)&h[0];
    *(uint4*)(o + 8)  = *(uint4*)&h[8];
    *(uint4*)(o + 64) = *(uint4*)&l[0];
    *(uint4*)(o + 72) = *(uint4*)&l[8];
}

// ---------------------------------------------------------------- X split
__global__ void k_xsplit(const float* __restrict__ X, __nv_bfloat16* __restrict__ Xs) {
    int i = blockIdx.x * blockDim.x + threadIdx.x;
    if (i >= NNODE * 8) return;
    int row = i >> 3, seg = i & 7;
    const float4* p = (const float4*)(X + (size_t)row * DIM + seg * 8);
    float4 v0 = p[0], v1 = p[1];
    float vv[8] = {v0.x, v0.y, v0.z, v0.w, v1.x, v1.y, v1.z, v1.w};
    __nv_bfloat16 h[8], l[8];
#pragma unroll
    for (int j = 0; j < 8; j++) {
        __nv_bfloat16 hh = __float2bfloat16_rn(vv[j]);
        h[j] = hh;
        l[j] = __float2bfloat16_rn(vv[j] - __bfloat162float(hh));
    }
    __nv_bfloat16* o = Xs + (size_t)row * 128 + seg * 8;
    *(uint4*)o        = *(uint4*)h;
    *(uint4*)(o + 64) = *(uint4*)l;
}

// ---------------------------------------------------------------- relu + split (layer boundary)
__global__ void k_relu_split(const float* __restrict__ O, __nv_bfloat16* __restrict__ Xs) {
    int i = blockIdx.x * blockDim.x + threadIdx.x;
    if (i >= NNODE * 8) return;
    int row = i >> 3, seg = i & 7;
    const float4* p = (const float4*)(O + (size_t)row * DIM + seg * 8);
    float4 v0 = p[0], v1 = p[1];
    float vv[8] = {fmaxf(v0.x, 0.f), fmaxf(v0.y, 0.f), fmaxf(v0.z, 0.f), fmaxf(v0.w, 0.f),
                   fmaxf(v1.x, 0.f), fmaxf(v1.y, 0.f), fmaxf(v1.z, 0.f), fmaxf(v1.w, 0.f)};
    __nv_bfloat16 h[8], l[8];
#pragma unroll
    for (int j = 0; j < 8; j++) {
        __nv_bfloat16 hh = __float2bfloat16_rn(vv[j]);
        h[j] = hh;
        l[j] = __float2bfloat16_rn(vv[j] - __bfloat162float(hh));
    }
    __nv_bfloat16* o = Xs + (size_t)row * 128 + seg * 8;
    *(uint4*)o        = *(uint4*)h;
    *(uint4*)(o + 64) = *(uint4*)l;
}

// ---------------------------------------------------------------- edge kernel (cp.async gather)
__global__ void __launch_bounds__(256, 3) k_edges(const __nv_bfloat16* __restrict__ Xs,
                                                  const __nv_bfloat16* __restrict__ Ws,
                                                  float* __restrict__ O) {
    int t = blockIdx.x;
    if (t >= g_numTiles) return;
    int r  = g_tileRel[t];
    int s0 = g_tileStart[t];
    int m  = min(g_relOff[r + 1] - s0, TILE);

    extern __shared__ char smem[];
    uint32_t sb = smem_u32(smem);
    int*   sDst  = (int*)(smem + SM_DST);
    float* sNorm = (float*)(smem + SM_NRM);
    int tid = threadIdx.x;

    // ---- B tile via cp.async (4 x 16B per thread) ----
    {
        int n = tid >> 2, c = tid & 3;
        const char* wr = (const char*)(Ws + ((size_t)(r * DIM + n) * 128 + (c & 1) * 32 + (c >> 1) * 64));
        uint32_t db = sb + ((c >> 1) ? SM_BL : SM_BH) + n * 144 + (c & 1) * 64;
#pragma unroll
        for (int j = 0; j < 4; j++) CP16(db + j * 16, wr + j * 16);
    }
    // ---- A gather via cp.async (2 threads per row, 8 x 16B each) ----
    {
        int e = tid >> 1, half = tid & 1;
        uint32_t ah = sb + SM_AH + e * 144 + half * 64;
        uint32_t al = sb + SM_AL + e * 144 + half * 64;
        if (e < m) {
            int sr = g_srcP[s0 + e];
            if (half == 0) { sDst[e] = g_dstP[s0 + e]; sNorm[e] = g_normP[s0 + e]; }
            const char* xr = (const char*)(Xs + (size_t)sr * 128) + half * 64;
#pragma unroll
            for (int j = 0; j < 4; j++) CP16(ah + j * 16, xr + j * 16);
#pragma unroll
            for (int j = 0; j < 4; j++) CP16(al + j * 16, xr + 128 + j * 16);
        } else {
            uint4 z = make_uint4(0, 0, 0, 0);
#pragma unroll
            for (int j = 0; j < 4; j++) {
                *(uint4*)(smem + SM_AH + e * 144 + half * 64 + j * 16) = z;
                *(uint4*)(smem + SM_AL + e * 144 + half * 64 + j * 16) = z;
            }
        }
    }
    CP_COMMIT();
    CP_WAIT0();
    __syncthreads();

    int lane = tid & 31, wid = tid >> 5;
    int g = lane >> 2, tg = lane & 3;
    int m0 = wid * 16;

    float c[8][4];
#pragma unroll
    for (int n = 0; n < 8; n++) { c[n][0] = 0.f; c[n][1] = 0.f; c[n][2] = 0.f; c[n][3] = 0.f; }

#pragma unroll
    for (int ks = 0; ks < 4; ks++) {
        int k0 = ks * 16;
        uint32_t ah[4], al[4];
        {
            const char* pLo = smem + SM_AH + ((m0 + g) * SAK + k0 + 2 * tg) * 2;
            const char* pHi = pLo + 8 * SAK * 2;
            ah[0] = *(const uint32_t*)pLo;  ah[1] = *(const uint32_t*)pHi;
            ah[2] = *(const uint32_t*)(pLo + 16); ah[3] = *(const uint32_t*)(pHi + 16);
            const char* qLo = smem + SM_AL + ((m0 + g) * SAK + k0 + 2 * tg) * 2;
            const char* qHi = qLo + 8 * SAK * 2;
            al[0] = *(const uint32_t*)qLo;  al[1] = *(const uint32_t*)qHi;
            al[2] = *(const uint32_t*)(qLo + 16); al[3] = *(const uint32_t*)(qHi + 16);
        }
#pragma unroll
        for (int n = 0; n < 8; n++) {
            uint32_t off = (uint32_t)((n * 8 + g) * SBK + k0 + 2 * tg) * 2;
            uint32_t bh0 = *(const uint32_t*)(smem + SM_BH + off);
            uint32_t bh1 = *(const uint32_t*)(smem + SM_BH + off + 16);
            uint32_t bl0 = *(const uint32_t*)(smem + SM_BL + off);
            uint32_t bl1 = *(const uint32_t*)(smem + SM_BL + off + 16);
            MMA_BF16(c[n], ah, bh0, bh1);
            MMA_BF16(c[n], al, bh0, bh1);
            MMA_BF16(c[n], ah, bl0, bl1);
        }
    }

    // epilogue: norm, shfl-pair, red.global.add.v4
    int  col0 = (tg & 2) * 2;
    bool lead = (tg & 1) == 0;
    int rA = m0 + g, rB = rA + 8;
    int dA = (rA < m) ? sDst[rA] : -1;
    int dB = (rB < m) ? sDst[rB] : -1;
    float nA = (rA < m) ? sNorm[rA] : 0.f;
    float nB = (rB < m) ? sNorm[rB] : 0.f;
#pragma unroll
    for (int n = 0; n < 8; n++) {
        float x0 = c[n][0] * nA, y0 = c[n][1] * nA;
        float x1 = c[n][2] * nB, y1 = c[n][3] * nB;
        float qx0 = __shfl_xor_sync(0xffffffffu, x0, 1);
        float qy0 = __shfl_xor_sync(0xffffffffu, y0, 1);
        float qx1 = __shfl_xor_sync(0xffffffffu, x1, 1);
        float qy1 = __shfl_xor_sync(0xffffffffu, y1, 1);
        if (lead && dA >= 0) {
            float* o = O + (size_t)dA * DIM + n * 8 + col0;
            asm volatile("red.global.add.v4.f32 [%0], {%1,%2,%3,%4};"
                         :: "l"(o), "f"(x0), "f"(y0), "f"(qx0), "f"(qy0) : "memory");
        }
        if (lead && dB >= 0) {
            float* o = O + (size_t)dB * DIM + n * 8 + col0;
            asm volatile("red.global.add.v4.f32 [%0], {%1,%2,%3,%4};"
                         :: "l"(o), "f"(x1), "f"(y1), "f"(qx1), "f"(qy1) : "memory");
        }
    }
}

// ---------------------------------------------------------------- self-loop: O = X @ Wl (direct write)
__global__ void __launch_bounds__(256, 3) k_selfloop(const __nv_bfloat16* __restrict__ Xs,
                                                     const __nv_bfloat16* __restrict__ Ws,
                                                     float* __restrict__ O) {
    int base = blockIdx.x * TILE;
    int m = min(TILE, NNODE - base);
    extern __shared__ char smem[];
    uint32_t sb = smem_u32(smem);
    int tid = threadIdx.x;

    {
        int n = tid >> 2, c = tid & 3;
        const char* wr = (const char*)(Ws + ((size_t)(NREL * DIM + n) * 128 + (c & 1) * 32 + (c >> 1) * 64));
        uint32_t db = sb + ((c >> 1) ? SM_BL : SM_BH) + n * 144 + (c & 1) * 64;
#pragma unroll
        for (int j = 0; j < 4; j++) CP16(db + j * 16, wr + j * 16);
    }
    {
        int e = tid >> 1, half = tid & 1;
        uint32_t ah = sb + SM_AH + e * 144 + half * 64;
        uint32_t al = sb + SM_AL + e * 144 + half * 64;
        if (e < m) {
            const char* xr = (const char*)(Xs + (size_t)(base + e) * 128) + half * 64;
#pragma unroll
            for (int j = 0; j < 4; j++) CP16(ah + j * 16, xr + j * 16);
#pragma unroll
            for (int j = 0; j < 4; j++) CP16(al + j * 16, xr + 128 + j * 16);
        } else {
            uint4 z = make_uint4(0, 0, 0, 0);
#pragma unroll
            for (int j = 0; j < 4; j++) {
                *(uint4*)(smem + SM_AH + e * 144 + half * 64 + j * 16) = z;
                *(uint4*)(smem + SM_AL + e * 144 + half * 64 + j * 16) = z;
            }
        }
    }
    CP_COMMIT();
    CP_WAIT0();
    __syncthreads();

    int lane = tid & 31, wid = tid >> 5;
    int g = lane >> 2, tg = lane & 3;
    int m0 = wid * 16;

    float c[8][4];
#pragma unroll
    for (int n = 0; n < 8; n++) { c[n][0] = 0.f; c[n][1] = 0.f; c[n][2] = 0.f; c[n][3] = 0.f; }

#pragma unroll
    for (int ks = 0; ks < 4; ks++) {
        int k0 = ks * 16;
        uint32_t ah[4], al[4];
        {
            const char* pLo = smem + SM_AH + ((m0 + g) * SAK + k0 + 2 * tg) * 2;
            const char* pHi = pLo + 8 * SAK * 2;
            ah[0] = *(const uint32_t*)pLo;  ah[1] = *(const uint32_t*)pHi;
            ah[2] = *(const uint32_t*)(pLo + 16); ah[3] = *(const uint32_t*)(pHi + 16);
            const char* qLo = smem + SM_AL + ((m0 + g) * SAK + k0 + 2 * tg) * 2;
            const char* qHi = qLo + 8 * SAK * 2;
            al[0] = *(const uint32_t*)qLo;  al[1] = *(const uint32_t*)qHi;
            al[2] = *(const uint32_t*)(qLo + 16); al[3] = *(const uint32_t*)(qHi + 16);
        }
#pragma unroll
        for (int n = 0; n < 8; n++) {
            uint32_t off = (uint32_t)((n * 8 + g) * SBK + k0 + 2 * tg) * 2;
            uint32_t bh0 = *(const uint32_t*)(smem + SM_BH + off);
            uint32_t bh1 = *(const uint32_t*)(smem + SM_BH + off + 16);
            uint32_t bl0 = *(const uint32_t*)(smem + SM_BL + off);
            uint32_t bl1 = *(const uint32_t*)(smem + SM_BL + off + 16);
            MMA_BF16(c[n], ah, bh0, bh1);
            MMA_BF16(c[n], al, bh0, bh1);
            MMA_BF16(c[n], ah, bl0, bl1);
        }
    }

    int  col0 = (tg & 2) * 2;
    bool lead = (tg & 1) == 0;
    int rA = m0 + g, rB = rA + 8;
    bool okA = rA < m, okB = rB < m;
#pragma unroll
    for (int n = 0; n < 8; n++) {
        float x0 = c[n][0], y0 = c[n][1];
        float x1 = c[n][2], y1 = c[n][3];
        float qx0 = __shfl_xor_sync(0xffffffffu, x0, 1);
        float qy0 = __shfl_xor_sync(0xffffffffu, y0, 1);
        float qx1 = __shfl_xor_sync(0xffffffffu, x1, 1);
        float qy1 = __shfl_xor_sync(0xffffffffu, y1, 1);
        if (lead && okA)
            *(float4*)(O + (size_t)(base + rA) * DIM + n * 8 + col0) = make_float4(x0, y0, qx0, qy0);
        if (lead && okB)
            *(float4*)(O + (size_t)(base + rB) * DIM + n * 8 + col0) = make_float4(x1, y1, qx1, qy1);
    }
}

// ---------------------------------------------------------------- relu (final)
__global__ void k_relu(float* __restrict__ O, int n4) {
    int i = blockIdx.x * blockDim.x + threadIdx.x;
    if (i < n4) {
        float4 v = ((float4*)O)[i];
        v.x = fmaxf(v.x, 0.f); v.y = fmaxf(v.y, 0.f);
        v.z = fmaxf(v.z, 0.f); v.w = fmaxf(v.w, 0.f);
        ((float4*)O)[i] = v;
    }
}

// ---------------------------------------------------------------- launch
extern "C" void kernel_launch(void* const* d_in, const int* in_sizes, int n_in,
                              void* d_out, int out_size) {
    const float* x   = (const float*)d_in[0];
    const int*   src = (const int*)d_in[1];
    const int*   dst = (const int*)d_in[2];
    const int*   et  = (const int*)d_in[3];
    const float* W1  = (const float*)d_in[4];
    const float* Wl1 = (const float*)d_in[5];
    const float* W2  = (const float*)d_in[6];
    const float* Wl2 = (const float*)d_in[7];
    float* out = (float*)d_out;

    void* p;
    cudaGetSymbolAddress(&p, g_h);   float* h  = (float*)p;
    cudaGetSymbolAddress(&p, g_Xs);  __nv_bfloat16* Xs = (__nv_bfloat16*)p;
    cudaGetSymbolAddress(&p, g_Hs);  __nv_bfloat16* Hs = (__nv_bfloat16*)p;
    cudaGetSymbolAddress(&p, g_Ws1); __nv_bfloat16* Ws1 = (__nv_bfloat16*)p;
    cudaGetSymbolAddress(&p, g_Ws2); __nv_bfloat16* Ws2 = (__nv_bfloat16*)p;
    void* cntp;
    cudaGetSymbolAddress(&cntp, g_cnt);

    cudaFuncSetAttribute(k_edges,    cudaFuncAttributeMaxDynamicSharedMemorySize, SM_TOT);
    cudaFuncSetAttribute(k_selfloop, cudaFuncAttributeMaxDynamicSharedMemorySize, SM_TOT);

    const int TPB = 256;
    // preprocessing: contention-free counting sort + pre-splits
    cudaMemsetAsync(cntp, 0, (size_t)NNODE * NREL * sizeof(int));
    k_hist<<<NB, TPB>>>(dst, et);
    k_scanRel<<<NREL, 128>>>();
    k_scan<<<1, 128>>>();
    k_tiles<<<(NTILES_MAX + 127) / 128, 128>>>();
    k_scatter<<<NB, TPB>>>(src, dst, et);
    k_wsplit<<<2 * (NREL + 1), 256>>>(W1, Wl1, W2, Wl2, Ws1, Ws2);
    k_xsplit<<<(NNODE * 8 + 255) / 256, 256>>>(x, Xs);

    int nBlocksRows = (NNODE + TILE - 1) / TILE;
    int n4 = NNODE * DIM / 4;

    // layer 1: h = relu(edges(x,W1) + x@Wl1)
    k_selfloop<<<nBlocksRows, TPB, SM_TOT>>>(Xs, Ws1, h);
    k_edges<<<NTILES_MAX, TPB, SM_TOT>>>(Xs, Ws1, h);
    k_relu_split<<<(NNODE * 8 + 255) / 256, 256>>>(h, Hs);

    // layer 2: out = relu(edges(h,W2) + h@Wl2)
    k_selfloop<<<nBlocksRows, TPB, SM_TOT>>>(Hs, Ws2, out);
    k_edges<<<NTILES_MAX, TPB, SM_TOT>>>(Hs, Ws2, out);
    k_relu<<<(n4 + TPB - 1) / TPB, TPB>>>(out, n4);
}

// round 9
// speedup vs baseline: 1.3193x; 1.0290x over previous
#include <cuda_runtime.h>
#include <cuda_bf16.h>
#include <cstdint>

#define NNODE 50000
#define NEDGE 800000
#define DIM   64
#define NREL  65
#define TILE  128
#define EPB   2048
#define NB    ((NEDGE + EPB - 1) / EPB)
#define NTILES_MAX ((NEDGE + TILE - 1) / TILE + NREL)
#define SAK   72    // smem row stride in bf16 units (144B; conflict-free)
#define SBK   72

// ---- scratch (static device globals; no allocation) ----
__device__ int   g_cnt[NNODE * NREL];
__device__ int   g_blockHist[NB * NREL];
__device__ int   g_relCnt[NREL];
__device__ int   g_relOff[NREL + 1];
__device__ int   g_tileBase[NREL + 1];
__device__ int   g_tileRel[NTILES_MAX];
__device__ int   g_tileStart[NTILES_MAX];
__device__ int   g_numTiles;
__device__ int   g_srcP[NEDGE];
__device__ int   g_dstP[NEDGE];
__device__ float g_normP[NEDGE];
__device__ float g_h[NNODE * DIM];
// pre-split bf16 buffers: row = 128 bf16 (hi[0:64], lo[64:128]) = 256B
__device__ __nv_bfloat16 g_Xs[(size_t)NNODE * 128];
__device__ __nv_bfloat16 g_Hs[(size_t)NNODE * 128];
// W splits: 66 slots (65 relations + self-loop W), [slot][n][128]: hi(k) 0:64, lo(k) 64:128
__device__ __nv_bfloat16 g_Ws1[(size_t)(NREL + 1) * DIM * 128];
__device__ __nv_bfloat16 g_Ws2[(size_t)(NREL + 1) * DIM * 128];

#define MMA_BF16(c, a, b0, b1)                                                   \
    asm volatile("mma.sync.aligned.m16n8k16.row.col.f32.bf16.bf16.f32 "          \
                 "{%0,%1,%2,%3},{%4,%5,%6,%7},{%8,%9},{%0,%1,%2,%3};"            \
                 : "+f"(c[0]), "+f"(c[1]), "+f"(c[2]), "+f"(c[3])                \
                 : "r"(a[0]), "r"(a[1]), "r"(a[2]), "r"(a[3]), "r"(b0), "r"(b1))

#define CP16(dst_u32, src_ptr)                                                   \
    asm volatile("cp.async.cg.shared.global [%0], [%1], 16;"                     \
                 :: "r"(dst_u32), "l"(src_ptr))
#define CP_COMMIT() asm volatile("cp.async.commit_group;")
#define CP_WAIT0()  asm volatile("cp.async.wait_group 0;")

__device__ __forceinline__ uint32_t smem_u32(const void* p) {
    uint32_t a;
    asm("{ .reg .u64 t; cvta.to.shared.u64 t, %1; cvt.u32.u64 %0, t; }"
        : "=r"(a) : "l"(p));
    return a;
}

// SMEM layout (bytes)
#define SM_DST  0
#define SM_NRM  512
#define SM_AH   1024
#define ASZ     (TILE * SAK * 2)                 // 18432
#define SM_AL   (SM_AH + ASZ + 16)               // 19472
#define SM_BH   (SM_AL + ASZ + 16)               // 37920
#define BSZ     (DIM * SBK * 2)                  // 9216
#define SM_BL   (SM_BH + BSZ + 16)               // 47152
#define SM_TOT  (SM_BL + BSZ)                    // 56368

// ---------------------------------------------------------------- histogram
__global__ void __launch_bounds__(256) k_hist(const int* __restrict__ dst,
                                              const int* __restrict__ et) {
    __shared__ int h[NREL];
    int tid = threadIdx.x, b = blockIdx.x;
    if (tid < NREL) h[tid] = 0;
    __syncthreads();
    int s = b * EPB, e_end = min(s + EPB, NEDGE);
    for (int e = s + tid; e < e_end; e += 256) {
        int r = et[e];
        atomicAdd(&h[r], 1);
        atomicAdd(&g_cnt[dst[e] * NREL + r], 1);
    }
    __syncthreads();
    if (tid < NREL) g_blockHist[b * NREL + tid] = h[tid];
}

// ---------------------------------------------------------------- per-relation block scan (parallel)
__global__ void __launch_bounds__(128) k_scanRel() {
    __shared__ int ts[128];
    int r = blockIdx.x, t = threadIdx.x;
    int base = t * 4;
    int v[4];
#pragma unroll
    for (int i = 0; i < 4; i++)
        v[i] = (base + i < NB) ? g_blockHist[(base + i) * NREL + r] : 0;
    int sum = v[0] + v[1] + v[2] + v[3];
    ts[t] = sum;
    __syncthreads();
    for (int off = 1; off < 128; off <<= 1) {
        int add = (t >= off) ? ts[t - off] : 0;
        __syncthreads();
        ts[t] += add;
        __syncthreads();
    }
    if (t == 127) g_relCnt[r] = ts[127];
    int run = ts[t] - sum;
#pragma unroll
    for (int i = 0; i < 4; i++) {
        if (base + i < NB) {
            int tmp = v[i];
            g_blockHist[(base + i) * NREL + r] = run;
            run += tmp;
        }
    }
}

// ---------------------------------------------------------------- relation offsets (parallel scan)
__global__ void k_scan() {
    __shared__ int a[128], b2[128];
    int t = threadIdx.x;
    int c  = (t < NREL) ? g_relCnt[t] : 0;
    int nt = (c + TILE - 1) / TILE;
    a[t] = c; b2[t] = nt;
    __syncthreads();
    for (int off = 1; off < 128; off <<= 1) {
        int av = a[t], bv = b2[t];
        int au = (t >= off) ? a[t - off] : 0;
        int bu = (t >= off) ? b2[t - off] : 0;
        __syncthreads();
        a[t] = av + au; b2[t] = bv + bu;
        __syncthreads();
    }
    if (t < NREL) { g_relOff[t] = a[t] - c; g_tileBase[t] = b2[t] - nt; }
    if (t == NREL - 1) {
        g_relOff[NREL] = a[t];
        g_tileBase[NREL] = b2[t];
        g_numTiles = b2[t];
    }
}

// ---------------------------------------------------------------- parallel tile table
__global__ void k_tiles() {
    int t = blockIdx.x * blockDim.x + threadIdx.x;
    if (t >= g_numTiles) return;
    int lo = 0, hi = NREL;
    while (lo + 1 < hi) {
        int mid = (lo + hi) >> 1;
        if (g_tileBase[mid] <= t) lo = mid; else hi = mid;
    }
    g_tileRel[t]   = lo;
    g_tileStart[t] = g_relOff[lo] + (t - g_tileBase[lo]) * TILE;
}

// ---------------------------------------------------------------- scatter sorted arrays
__global__ void __launch_bounds__(256) k_scatter(const int* __restrict__ src,
                                                 const int* __restrict__ dst,
                                                 const int* __restrict__ et) {
    __shared__ int cur[NREL];
    int tid = threadIdx.x, b = blockIdx.x;
    if (tid < NREL) cur[tid] = g_relOff[tid] + g_blockHist[b * NREL + tid];
    __syncthreads();
    int s = b * EPB, e_end = min(s + EPB, NEDGE);
    for (int e = s + tid; e < e_end; e += 256) {
        int r = et[e], d = dst[e];
        int pos = atomicAdd(&cur[r], 1);
        g_srcP[pos]  = src[e];
        g_dstP[pos]  = d;
        g_normP[pos] = 1.0f / (float)max(g_cnt[d * NREL + r], 1);
    }
}

// ---------------------------------------------------------------- W split (both layers in one launch)
__global__ void __launch_bounds__(256) k_wsplit(const float* __restrict__ W1,
                                                const float* __restrict__ Wl1,
                                                const float* __restrict__ W2,
                                                const float* __restrict__ Wl2,
                                                __nv_bfloat16* __restrict__ o1,
                                                __nv_bfloat16* __restrict__ o2) {
    int rb = blockIdx.x;
    int layer = rb >= (NREL + 1);
    int r = layer ? rb - (NREL + 1) : rb;
    const float* W  = layer ? W2 : W1;
    const float* Wl = layer ? Wl2 : Wl1;
    __nv_bfloat16* out = layer ? o2 : o1;
    const float* src = (r < NREL) ? (W + (size_t)r * DIM * DIM) : Wl;
    int t = threadIdx.x;
    int n = t >> 2, kc = (t & 3) * 16;
    __nv_bfloat16 h[16], l[16];
#pragma unroll
    for (int kk = 0; kk < 16; kk++) {
        float v = src[(kc + kk) * DIM + n];
        __nv_bfloat16 hh = __float2bfloat16_rn(v);
        h[kk] = hh;
        l[kk] = __float2bfloat16_rn(v - __bfloat162float(hh));
    }
    __nv_bfloat16* o = out + ((size_t)(r * DIM + n) * 128 + kc);
    *(uint4*)o        = *(uint4*)&h[0];
    *(uint4*)(o + 8)  = *(uint4*)&h[8];
    *(uint4*)(o + 64) = *(uint4*)&l[0];
    *(uint4*)(o + 72) = *(uint4*)&l[8];
}

// ---------------------------------------------------------------- X split
__global__ void k_xsplit(const float* __restrict__ X, __nv_bfloat16* __restrict__ Xs) {
    int i = blockIdx.x * blockDim.x + threadIdx.x;
    if (i >= NNODE * 8) return;
    int row = i >> 3, seg = i & 7;
    const float4* p = (const float4*)(X + (size_t)row * DIM + seg * 8);
    float4 v0 = p[0], v1 = p[1];
    float vv[8] = {v0.x, v0.y, v0.z, v0.w, v1.x, v1.y, v1.z, v1.w};
    __nv_bfloat16 h[8], l[8];
#pragma unroll
    for (int j = 0; j < 8; j++) {
        __nv_bfloat16 hh = __float2bfloat16_rn(vv[j]);
        h[j] = hh;
        l[j] = __float2bfloat16_rn(vv[j] - __bfloat162float(hh));
    }
    __nv_bfloat16* o = Xs + (size_t)row * 128 + seg * 8;
    *(uint4*)o        = *(uint4*)h;
    *(uint4*)(o + 64) = *(uint4*)l;
}

// ---------------------------------------------------------------- relu + split (layer boundary)
__global__ void k_relu_split(const float* __restrict__ O, __nv_bfloat16* __restrict__ Xs) {
    int i = blockIdx.x * blockDim.x + threadIdx.x;
    if (i >= NNODE * 8) return;
    int row = i >> 3, seg = i & 7;
    const float4* p = (const float4*)(O + (size_t)row * DIM + seg * 8);
    float4 v0 = p[0], v1 = p[1];
    float vv[8] = {fmaxf(v0.x, 0.f), fmaxf(v0.y, 0.f), fmaxf(v0.z, 0.f), fmaxf(v0.w, 0.f),
                   fmaxf(v1.x, 0.f), fmaxf(v1.y, 0.f), fmaxf(v1.z, 0.f), fmaxf(v1.w, 0.f)};
    __nv_bfloat16 h[8], l[8];
#pragma unroll
    for (int j = 0; j < 8; j++) {
        __nv_bfloat16 hh = __float2bfloat16_rn(vv[j]);
        h[j] = hh;
        l[j] = __float2bfloat16_rn(vv[j] - __bfloat162float(hh));
    }
    __nv_bfloat16* o = Xs + (size_t)row * 128 + seg * 8;
    *(uint4*)o        = *(uint4*)h;
    *(uint4*)(o + 64) = *(uint4*)l;
}

// ---------------------------------------------------------------- edge kernel (cp.async gather)
__global__ void __launch_bounds__(256, 3) k_edges(const __nv_bfloat16* __restrict__ Xs,
                                                  const __nv_bfloat16* __restrict__ Ws,
                                                  float* __restrict__ O) {
    int t = blockIdx.x;
    if (t >= g_numTiles) return;
    int r  = g_tileRel[t];
    int s0 = g_tileStart[t];
    int m  = min(g_relOff[r + 1] - s0, TILE);

    extern __shared__ char smem[];
    uint32_t sb = smem_u32(smem);
    int*   sDst  = (int*)(smem + SM_DST);
    float* sNorm = (float*)(smem + SM_NRM);
    int tid = threadIdx.x;

    // ---- B tile via cp.async (4 x 16B per thread) ----
    {
        int n = tid >> 2, c = tid & 3;
        const char* wr = (const char*)(Ws + ((size_t)(r * DIM + n) * 128 + (c & 1) * 32 + (c >> 1) * 64));
        uint32_t db = sb + ((c >> 1) ? SM_BL : SM_BH) + n * 144 + (c & 1) * 64;
#pragma unroll
        for (int j = 0; j < 4; j++) CP16(db + j * 16, wr + j * 16);
    }
    // ---- A gather via cp.async (2 threads per row, 8 x 16B each) ----
    {
        int e = tid >> 1, half = tid & 1;
        uint32_t ah = sb + SM_AH + e * 144 + half * 64;
        uint32_t al = sb + SM_AL + e * 144 + half * 64;
        if (e < m) {
            int sr = g_srcP[s0 + e];
            if (half == 0) { sDst[e] = g_dstP[s0 + e]; sNorm[e] = g_normP[s0 + e]; }
            const char* xr = (const char*)(Xs + (size_t)sr * 128) + half * 64;
#pragma unroll
            for (int j = 0; j < 4; j++) CP16(ah + j * 16, xr + j * 16);
#pragma unroll
            for (int j = 0; j < 4; j++) CP16(al + j * 16, xr + 128 + j * 16);
        } else {
            uint4 z = make_uint4(0, 0, 0, 0);
#pragma unroll
            for (int j = 0; j < 4; j++) {
                *(uint4*)(smem + SM_AH + e * 144 + half * 64 + j * 16) = z;
                *(uint4*)(smem + SM_AL + e * 144 + half * 64 + j * 16) = z;
            }
        }
    }
    CP_COMMIT();
    CP_WAIT0();
    __syncthreads();

    int lane = tid & 31, wid = tid >> 5;
    int g = lane >> 2, tg = lane & 3;
    int m0 = wid * 16;

    float c[8][4];
#pragma unroll
    for (int n = 0; n < 8; n++) { c[n][0] = 0.f; c[n][1] = 0.f; c[n][2] = 0.f; c[n][3] = 0.f; }

#pragma unroll
    for (int ks = 0; ks < 4; ks++) {
        int k0 = ks * 16;
        uint32_t ah[4], al[4];
        {
            const char* pLo = smem + SM_AH + ((m0 + g) * SAK + k0 + 2 * tg) * 2;
            const char* pHi = pLo + 8 * SAK * 2;
            ah[0] = *(const uint32_t*)pLo;  ah[1] = *(const uint32_t*)pHi;
            ah[2] = *(const uint32_t*)(pLo + 16); ah[3] = *(const uint32_t*)(pHi + 16);
            const char* qLo = smem + SM_AL + ((m0 + g) * SAK + k0 + 2 * tg) * 2;
            const char* qHi = qLo + 8 * SAK * 2;
            al[0] = *(const uint32_t*)qLo;  al[1] = *(const uint32_t*)qHi;
            al[2] = *(const uint32_t*)(qLo + 16); al[3] = *(const uint32_t*)(qHi + 16);
        }
#pragma unroll
        for (int n = 0; n < 8; n++) {
            uint32_t off = (uint32_t)((n * 8 + g) * SBK + k0 + 2 * tg) * 2;
            uint32_t bh0 = *(const uint32_t*)(smem + SM_BH + off);
            uint32_t bh1 = *(const uint32_t*)(smem + SM_BH + off + 16);
            uint32_t bl0 = *(const uint32_t*)(smem + SM_BL + off);
            uint32_t bl1 = *(const uint32_t*)(smem + SM_BL + off + 16);
            MMA_BF16(c[n], ah, bh0, bh1);
            MMA_BF16(c[n], al, bh0, bh1);
            MMA_BF16(c[n], ah, bl0, bl1);
        }
    }

    // epilogue: norm, shfl-pair, red.global.add.v4
    int  col0 = (tg & 2) * 2;
    bool lead = (tg & 1) == 0;
    int rA = m0 + g, rB = rA + 8;
    int dA = (rA < m) ? sDst[rA] : -1;
    int dB = (rB < m) ? sDst[rB] : -1;
    float nA = (rA < m) ? sNorm[rA] : 0.f;
    float nB = (rB < m) ? sNorm[rB] : 0.f;
#pragma unroll
    for (int n = 0; n < 8; n++) {
        float x0 = c[n][0] * nA, y0 = c[n][1] * nA;
        float x1 = c[n][2] * nB, y1 = c[n][3] * nB;
        float qx0 = __shfl_xor_sync(0xffffffffu, x0, 1);
        float qy0 = __shfl_xor_sync(0xffffffffu, y0, 1);
        float qx1 = __shfl_xor_sync(0xffffffffu, x1, 1);
        float qy1 = __shfl_xor_sync(0xffffffffu, y1, 1);
        if (lead && dA >= 0) {
            float* o = O + (size_t)dA * DIM + n * 8 + col0;
            asm volatile("red.global.add.v4.f32 [%0], {%1,%2,%3,%4};"
                         :: "l"(o), "f"(x0), "f"(y0), "f"(qx0), "f"(qy0) : "memory");
        }
        if (lead && dB >= 0) {
            float* o = O + (size_t)dB * DIM + n * 8 + col0;
            asm volatile("red.global.add.v4.f32 [%0], {%1,%2,%3,%4};"
                         :: "l"(o), "f"(x1), "f"(y1), "f"(qx1), "f"(qy1) : "memory");
        }
    }
}

// ---------------------------------------------------------------- self-loop: O = X @ Wl (direct write)
__global__ void __launch_bounds__(256, 3) k_selfloop(const __nv_bfloat16* __restrict__ Xs,
                                                     const __nv_bfloat16* __restrict__ Ws,
                                                     float* __restrict__ O) {
    int base = blockIdx.x * TILE;
    int m = min(TILE, NNODE - base);
    extern __shared__ char smem[];
    uint32_t sb = smem_u32(smem);
    int tid = threadIdx.x;

    {
        int n = tid >> 2, c = tid & 3;
        const char* wr = (const char*)(Ws + ((size_t)(NREL * DIM + n) * 128 + (c & 1) * 32 + (c >> 1) * 64));
        uint32_t db = sb + ((c >> 1) ? SM_BL : SM_BH) + n * 144 + (c & 1) * 64;
#pragma unroll
        for (int j = 0; j < 4; j++) CP16(db + j * 16, wr + j * 16);
    }
    {
        int e = tid >> 1, half = tid & 1;
        uint32_t ah = sb + SM_AH + e * 144 + half * 64;
        uint32_t al = sb + SM_AL + e * 144 + half * 64;
        if (e < m) {
            const char* xr = (const char*)(Xs + (size_t)(base + e) * 128) + half * 64;
#pragma unroll
            for (int j = 0; j < 4; j++) CP16(ah + j * 16, xr + j * 16);
#pragma unroll
            for (int j = 0; j < 4; j++) CP16(al + j * 16, xr + 128 + j * 16);
        } else {
            uint4 z = make_uint4(0, 0, 0, 0);
#pragma unroll
            for (int j = 0; j < 4; j++) {
                *(uint4*)(smem + SM_AH + e * 144 + half * 64 + j * 16) = z;
                *(uint4*)(smem + SM_AL + e * 144 + half * 64 + j * 16) = z;
            }
        }
    }
    CP_COMMIT();
    CP_WAIT0();
    __syncthreads();

    int lane = tid & 31, wid = tid >> 5;
    int g = lane >> 2, tg = lane & 3;
    int m0 = wid * 16;

    float c[8][4];
#pragma unroll
    for (int n = 0; n < 8; n++) { c[n][0] = 0.f; c[n][1] = 0.f; c[n][2] = 0.f; c[n][3] = 0.f; }

#pragma unroll
    for (int ks = 0; ks < 4; ks++) {
        int k0 = ks * 16;
        uint32_t ah[4], al[4];
        {
            const char* pLo = smem + SM_AH + ((m0 + g) * SAK + k0 + 2 * tg) * 2;
            const char* pHi = pLo + 8 * SAK * 2;
            ah[0] = *(const uint32_t*)pLo;  ah[1] = *(const uint32_t*)pHi;
            ah[2] = *(const uint32_t*)(pLo + 16); ah[3] = *(const uint32_t*)(pHi + 16);
            const char* qLo = smem + SM_AL + ((m0 + g) * SAK + k0 + 2 * tg) * 2;
            const char* qHi = qLo + 8 * SAK * 2;
            al[0] = *(const uint32_t*)qLo;  al[1] = *(const uint32_t*)qHi;
            al[2] = *(const uint32_t*)(qLo + 16); al[3] = *(const uint32_t*)(qHi + 16);
        }
#pragma unroll
        for (int n = 0; n < 8; n++) {
            uint32_t off = (uint32_t)((n * 8 + g) * SBK + k0 + 2 * tg) * 2;
            uint32_t bh0 = *(const uint32_t*)(smem + SM_BH + off);
            uint32_t bh1 = *(const uint32_t*)(smem + SM_BH + off + 16);
            uint32_t bl0 = *(const uint32_t*)(smem + SM_BL + off);
            uint32_t bl1 = *(const uint32_t*)(smem + SM_BL + off + 16);
            MMA_BF16(c[n], ah, bh0, bh1);
            MMA_BF16(c[n], al, bh0, bh1);
            MMA_BF16(c[n], ah, bl0, bl1);
        }
    }

    int  col0 = (tg & 2) * 2;
    bool lead = (tg & 1) == 0;
    int rA = m0 + g, rB = rA + 8;
    bool okA = rA < m, okB = rB < m;
#pragma unroll
    for (int n = 0; n < 8; n++) {
        float x0 = c[n][0], y0 = c[n][1];
        float x1 = c[n][2], y1 = c[n][3];
        float qx0 = __shfl_xor_sync(0xffffffffu, x0, 1);
        float qy0 = __shfl_xor_sync(0xffffffffu, y0, 1);
        float qx1 = __shfl_xor_sync(0xffffffffu, x1, 1);
        float qy1 = __shfl_xor_sync(0xffffffffu, y1, 1);
        if (lead && okA)
            *(float4*)(O + (size_t)(base + rA) * DIM + n * 8 + col0) = make_float4(x0, y0, qx0, qy0);
        if (lead && okB)
            *(float4*)(O + (size_t)(base + rB) * DIM + n * 8 + col0) = make_float4(x1, y1, qx1, qy1);
    }
}

// ---------------------------------------------------------------- relu (final)
__global__ void k_relu(float* __restrict__ O, int n4) {
    int i = blockIdx.x * blockDim.x + threadIdx.x;
    if (i < n4) {
        float4 v = ((float4*)O)[i];
        v.x = fmaxf(v.x, 0.f); v.y = fmaxf(v.y, 0.f);
        v.z = fmaxf(v.z, 0.f); v.w = fmaxf(v.w, 0.f);
        ((float4*)O)[i] = v;
    }
}

// ---------------------------------------------------------------- launch
extern "C" void kernel_launch(void* const* d_in, const int* in_sizes, int n_in,
                              void* d_out, int out_size) {
    const float* x   = (const float*)d_in[0];
    const int*   src = (const int*)d_in[1];
    const int*   dst = (const int*)d_in[2];
    const int*   et  = (const int*)d_in[3];
    const float* W1  = (const float*)d_in[4];
    const float* Wl1 = (const float*)d_in[5];
    const float* W2  = (const float*)d_in[6];
    const float* Wl2 = (const float*)d_in[7];
    float* out = (float*)d_out;

    void* p;
    cudaGetSymbolAddress(&p, g_h);   float* h  = (float*)p;
    cudaGetSymbolAddress(&p, g_Xs);  __nv_bfloat16* Xs = (__nv_bfloat16*)p;
    cudaGetSymbolAddress(&p, g_Hs);  __nv_bfloat16* Hs = (__nv_bfloat16*)p;
    cudaGetSymbolAddress(&p, g_Ws1); __nv_bfloat16* Ws1 = (__nv_bfloat16*)p;
    cudaGetSymbolAddress(&p, g_Ws2); __nv_bfloat16* Ws2 = (__nv_bfloat16*)p;
    void* cntp;
    cudaGetSymbolAddress(&cntp, g_cnt);

    cudaFuncSetAttribute(k_edges,    cudaFuncAttributeMaxDynamicSharedMemorySize, SM_TOT);
    cudaFuncSetAttribute(k_selfloop, cudaFuncAttributeMaxDynamicSharedMemorySize, SM_TOT);

    const int TPB = 256;
    int nBlocksRows = (NNODE + TILE - 1) / TILE;
    int n4 = NNODE * DIM / 4;

    // fork: side stream for the independent split/selfloop chain
    cudaStream_t s1;
    cudaStreamCreateWithFlags(&s1, cudaStreamNonBlocking);
    cudaEvent_t e0, e1;
    cudaEventCreateWithFlags(&e0, cudaEventDisableTiming);
    cudaEventCreateWithFlags(&e1, cudaEventDisableTiming);

    cudaEventRecord(e0, 0);
    cudaStreamWaitEvent(s1, e0, 0);

    // branch A (main stream): counting sort preprocessing
    cudaMemsetAsync(cntp, 0, (size_t)NNODE * NREL * sizeof(int));
    k_hist<<<NB, TPB>>>(dst, et);
    k_scanRel<<<NREL, 128>>>();
    k_scan<<<1, 128>>>();
    k_tiles<<<(NTILES_MAX + 127) / 128, 128>>>();
    k_scatter<<<NB, TPB>>>(src, dst, et);

    // branch B (side stream): splits + layer-1 self-loop (independent of sort)
    k_wsplit<<<2 * (NREL + 1), 256, 0, s1>>>(W1, Wl1, W2, Wl2, Ws1, Ws2);
    k_xsplit<<<(NNODE * 8 + 255) / 256, 256, 0, s1>>>(x, Xs);
    k_selfloop<<<nBlocksRows, TPB, SM_TOT, s1>>>(Xs, Ws1, h);

    // join
    cudaEventRecord(e1, s1);
    cudaStreamWaitEvent(0, e1, 0);

    // layer 1 edges: h += edges(x,W1); then relu+split
    k_edges<<<NTILES_MAX, TPB, SM_TOT>>>(Xs, Ws1, h);
    k_relu_split<<<(NNODE * 8 + 255) / 256, 256>>>(h, Hs);

    // layer 2: out = relu(edges(h,W2) + h@Wl2)
    k_selfloop<<<nBlocksRows, TPB, SM_TOT>>>(Hs, Ws2, out);
    k_edges<<<NTILES_MAX, TPB, SM_TOT>>>(Hs, Ws2, out);
    k_relu<<<(n4 + TPB - 1) / TPB, TPB>>>(out, n4);

    cudaEventDestroy(e0);
    cudaEventDestroy(e1);
    cudaStreamDestroy(s1);
}